// round 13
// baseline (speedup 1.0000x reference)
#include <cuda_runtime.h>
#include <cuda_bf16.h>
#include <cuda_fp16.h>
#include <cstdint>

#define F_IN  512
#define HID   16
#define C_OUT 40
#define MAXN  100000
#define MAXE  3200000

typedef unsigned long long ull;
typedef unsigned int u32;

// ---------------- scratch (static device globals, no allocs) ----------------
__device__ __align__(128) int    g_deg [MAXN];
__device__ __align__(128) float  g_dinv[MAXN];
__device__ __align__(128) __half g_B1h [MAXN * HID];  // fp16 message buffer
__device__ __align__(128) float  g_B2  [MAXN * HID];  // fp32 agg accumulators
__device__ __align__(128) float  g_W1h [F_IN * HID];  // tf32 hi part of W1
__device__ __align__(128) float  g_W1l [F_IN * HID];  // tf32 lo part of W1

// ---------------- helpers ----------------
__device__ __forceinline__ void red4(float* p, float a, float b, float c, float d) {
    asm volatile("red.global.add.v4.f32 [%0], {%1,%2,%3,%4};"
                 :: "l"(p), "f"(a), "f"(b), "f"(c), "f"(d) : "memory");
}
__device__ __forceinline__ u32 s2u(const void* p) {
    u32 a;
    asm("{ .reg .u64 t; cvta.to.shared.u64 t, %1; cvt.u32.u64 %0, t; }"
        : "=r"(a) : "l"(p));
    return a;
}
__device__ __forceinline__ void cpa16(u32 dst, const void* src, int sz) {
    asm volatile("cp.async.cg.shared.global [%0], [%1], 16, %2;"
                 :: "r"(dst), "l"(src), "r"(sz) : "memory");
}
__device__ __forceinline__ void cpa_commit() {
    asm volatile("cp.async.commit_group;" ::: "memory");
}
template <int NN>
__device__ __forceinline__ void cpa_wait() {
    asm volatile("cp.async.wait_group %0;" :: "n"(NN) : "memory");
}
__device__ __forceinline__ u32 tf32_of(float f) {
    u32 r;
    asm("cvt.rna.tf32.f32 %0, %1;" : "=r"(r) : "f"(f));
    return r;
}
__device__ __forceinline__ void tf32_split(float a, u32& hi, u32& lo) {
    hi = tf32_of(a);
    lo = tf32_of(a - __uint_as_float(hi));
}
__device__ __forceinline__ void mma_tf32(float& d0, float& d1, float& d2, float& d3,
                                         u32 a0, u32 a1, u32 a2, u32 a3,
                                         u32 b0, u32 b1) {
    asm("mma.sync.aligned.m16n8k8.row.col.f32.tf32.tf32.f32 "
        "{%0,%1,%2,%3}, {%4,%5,%6,%7}, {%8,%9}, {%0,%1,%2,%3};"
        : "+f"(d0), "+f"(d1), "+f"(d2), "+f"(d3)
        : "r"(a0), "r"(a1), "r"(a2), "r"(a3), "r"(b0), "r"(b1));
}

// ---------------- launch 0: fused zero(deg) + W1 tf32 split -----------------
__global__ void k_zero_ws(int* deg, const float* __restrict__ W1,
                          float* wh, float* wl, int N, int nw) {
    int i = blockIdx.x * blockDim.x + threadIdx.x;
    if (i < N) deg[i] = 0;
    if (i < nw) {
        float w = W1[i];
        u32 h, l;
        tf32_split(w, h, l);
        wh[i] = __uint_as_float(h);
        wl[i] = __uint_as_float(l);
    }
}
__global__ void k_hist(const int* __restrict__ dst, int* deg, int E) {
    int i = blockIdx.x * blockDim.x + threadIdx.x;
    if (i < E) atomicAdd(&deg[dst[i]], 1);
}
__global__ void k_dinv(const int* __restrict__ deg, float* dinv, int N) {
    int i = blockIdx.x * blockDim.x + threadIdx.x;
    if (i < N) dinv[i] = rsqrtf((float)(deg[i] + 1));
}

// ------ GEMM1 v8: tf32 mma, A-hi only (2-term), precomputed W split ---------
// error budget: drop a_lo*b_hi term -> ~2.4e-4 rel, combined ~3e-4 vs 1e-3.
#define G1_XS 36
#define G1_WS 24
__global__ __launch_bounds__(256) void k_gemm1(const float* __restrict__ x,
                                               const float* __restrict__ W1h,
                                               const float* __restrict__ W1l,
                                               const float* __restrict__ dinv,
                                               __half* __restrict__ h0h,
                                               float* __restrict__ h1, int N) {
    __shared__ __align__(16) float xs[2][128 * G1_XS];
    __shared__ __align__(16) float wh[2][32 * G1_WS];
    __shared__ __align__(16) float wl[2][32 * G1_WS];
    const int t    = threadIdx.x;
    const int lane = t & 31;
    const int wid  = t >> 5;
    const int gid  = lane >> 2;
    const int tig  = lane & 3;
    const int base = blockIdx.x * 128;

    u32 xdst[2][4];
    const float* xsrc[4];
    int xsz[4];
#pragma unroll
    for (int j = 0; j < 4; j++) {
        int idx = t + 256 * j;
        int r = idx >> 3, q = idx & 7;
        xdst[0][j] = s2u(&xs[0][r * G1_XS]) + q * 16;
        xdst[1][j] = s2u(&xs[1][r * G1_XS]) + q * 16;
        xsrc[j] = x + (size_t)(base + r) * F_IN + q * 4;
        xsz[j]  = (base + r < N) ? 16 : 0;
    }
    const int wk = (t & 127) >> 2, wq = t & 3;
    u32 wdst[2];
    const float* wsrcb;
    if (t < 128) {
        wdst[0] = s2u(&wh[0][wk * G1_WS]) + wq * 16;
        wdst[1] = s2u(&wh[1][wk * G1_WS]) + wq * 16;
        wsrcb = W1h + (size_t)wk * 16 + wq * 4;
    } else {
        wdst[0] = s2u(&wl[0][wk * G1_WS]) + wq * 16;
        wdst[1] = s2u(&wl[1][wk * G1_WS]) + wq * 16;
        wsrcb = W1l + (size_t)wk * 16 + wq * 4;
    }

    float d0[4] = {0.f, 0.f, 0.f, 0.f};
    float d1[4] = {0.f, 0.f, 0.f, 0.f};

    cpa16(wdst[0], wsrcb, 16);
#pragma unroll
    for (int j = 0; j < 4; j++) cpa16(xdst[0][j], xsrc[j], xsz[j]);
    cpa_commit();

    for (int kt = 0; kt < 16; kt++) {
        const int buf = kt & 1;
        if (kt < 15) {
            const int nb = buf ^ 1;
            const int kg = (kt + 1) * 32;
            cpa16(wdst[nb], wsrcb + (size_t)kg * 16, 16);
#pragma unroll
            for (int j = 0; j < 4; j++) cpa16(xdst[nb][j], xsrc[j] + kg, xsz[j]);
            cpa_commit();
            cpa_wait<1>();
        } else {
            cpa_wait<0>();
        }
        __syncthreads();

        const int ra = wid * 16 + gid;
#pragma unroll
        for (int s = 0; s < 4; s++) {
            const int ko = s * 8;
            float a0 = xs[buf][ra * G1_XS + ko + tig];
            float a1 = xs[buf][(ra + 8) * G1_XS + ko + tig];
            float a2 = xs[buf][ra * G1_XS + ko + tig + 4];
            float a3 = xs[buf][(ra + 8) * G1_XS + ko + tig + 4];
            u32 a0h = tf32_of(a0), a1h = tf32_of(a1);
            u32 a2h = tf32_of(a2), a3h = tf32_of(a3);
            u32 b0h = __float_as_uint(wh[buf][(ko + tig) * G1_WS + gid]);
            u32 b1h = __float_as_uint(wh[buf][(ko + tig + 4) * G1_WS + gid]);
            u32 b2h = __float_as_uint(wh[buf][(ko + tig) * G1_WS + gid + 8]);
            u32 b3h = __float_as_uint(wh[buf][(ko + tig + 4) * G1_WS + gid + 8]);
            u32 b0l = __float_as_uint(wl[buf][(ko + tig) * G1_WS + gid]);
            u32 b1l = __float_as_uint(wl[buf][(ko + tig + 4) * G1_WS + gid]);
            u32 b2l = __float_as_uint(wl[buf][(ko + tig) * G1_WS + gid + 8]);
            u32 b3l = __float_as_uint(wl[buf][(ko + tig + 4) * G1_WS + gid + 8]);

            // 2-term: a_hi*b_hi + a_hi*b_lo
            mma_tf32(d0[0], d0[1], d0[2], d0[3], a0h, a1h, a2h, a3h, b0h, b1h);
            mma_tf32(d1[0], d1[1], d1[2], d1[3], a0h, a1h, a2h, a3h, b2h, b3h);
            mma_tf32(d0[0], d0[1], d0[2], d0[3], a0h, a1h, a2h, a3h, b0l, b1l);
            mma_tf32(d1[0], d1[1], d1[2], d1[3], a0h, a1h, a2h, a3h, b2l, b3l);
        }
        __syncthreads();
    }

    {
        int r0 = base + wid * 16 + gid;
        int r1 = r0 + 8;
        if (r0 < N) {
            float dv = dinv[r0];
            float4 v = make_float4(d0[0] * dv, d0[1] * dv, d1[0] * dv, d1[1] * dv);
            *(__half2*)&h0h[(size_t)r0 * HID + 2 * tig]     = __floats2half2_rn(v.x, v.y);
            *(__half2*)&h0h[(size_t)r0 * HID + 8 + 2 * tig] = __floats2half2_rn(v.z, v.w);
            *(float2*)&h1[(size_t)r0 * HID + 2 * tig]     = make_float2(v.x, v.y);
            *(float2*)&h1[(size_t)r0 * HID + 8 + 2 * tig] = make_float2(v.z, v.w);
        }
        if (r1 < N) {
            float dv = dinv[r1];
            float4 v = make_float4(d0[2] * dv, d0[3] * dv, d1[2] * dv, d1[3] * dv);
            *(__half2*)&h0h[(size_t)r1 * HID + 2 * tig]     = __floats2half2_rn(v.x, v.y);
            *(__half2*)&h0h[(size_t)r1 * HID + 8 + 2 * tig] = __floats2half2_rn(v.z, v.w);
            *(float2*)&h1[(size_t)r1 * HID + 2 * tig]     = make_float2(v.x, v.y);
            *(float2*)&h1[(size_t)r1 * HID + 8 + 2 * tig] = make_float2(v.z, v.w);
        }
    }
}

// --- edge aggregation: fp16 gather (uint2/thread), fp32 red4, 4 thr/edge ---
__global__ void k_agg_h(const int* __restrict__ src, const int* __restrict__ dst,
                        const __half* __restrict__ inh, float* out, int E) {
    int tid = blockIdx.x * blockDim.x + threadIdx.x;
    int e = tid >> 2;
    int c = tid & 3;
    if (e < E) {
        int s = src[e];
        int d = dst[e];
        uint2 v = __ldg((const uint2*)(inh + (size_t)s * HID) + c);  // 4 halves
        float2 f0 = __half22float2(*(__half2*)&v.x);
        float2 f1 = __half22float2(*(__half2*)&v.y);
        red4(out + (size_t)d * HID + c * 4, f0.x, f0.y, f1.x, f1.y);
    }
}

// -------- a~ = dinv * relu(dinv * y1 + b1): fp16 -> o0h, fp32 -> o1 ---------
__global__ void k_relubias(const float4* __restrict__ in4, const float* __restrict__ dinv,
                           const float* __restrict__ b1,
                           __half* __restrict__ o0h, float4* __restrict__ o1, int N) {
    int i = blockIdx.x * blockDim.x + threadIdx.x;
    if (i < N * (HID / 4)) {
        float dv = dinv[i >> 2];
        int jb = (i & 3) * 4;
        float4 v = in4[i];
        v.x = fmaxf(fmaf(v.x, dv, b1[jb + 0]), 0.f) * dv;
        v.y = fmaxf(fmaf(v.y, dv, b1[jb + 1]), 0.f) * dv;
        v.z = fmaxf(fmaf(v.z, dv, b1[jb + 2]), 0.f) * dv;
        v.w = fmaxf(fmaf(v.w, dv, b1[jb + 3]), 0.f) * dv;
        __half2 ha = __floats2half2_rn(v.x, v.y);
        __half2 hb = __floats2half2_rn(v.z, v.w);
        *(uint2*)&o0h[(size_t)i * 4] = make_uint2(*(u32*)&ha, *(u32*)&hb);
        o1[i] = v;
    }
}

// ---------------- GEMM2 + b2 ----------------
__global__ __launch_bounds__(128) void k_gemm2(const float* __restrict__ y2,
                                               const float* __restrict__ dinv,
                                               const float* __restrict__ W2,
                                               const float* __restrict__ b2,
                                               float* __restrict__ out, int N) {
    __shared__ float w2s[HID * C_OUT];
    __shared__ float b2s[C_OUT];
    int t = threadIdx.x;
    for (int i = t; i < HID * C_OUT; i += 128) w2s[i] = W2[i];
    if (t < C_OUT) b2s[t] = b2[t];
    __syncthreads();
    int i = blockIdx.x * 128 + t;
    if (i >= N) return;
    float dv = dinv[i];
    float a[HID];
#pragma unroll
    for (int k4 = 0; k4 < 4; k4++) {
        float4 v = *(const float4*)&y2[(size_t)i * HID + 4 * k4];
        a[4 * k4 + 0] = v.x * dv; a[4 * k4 + 1] = v.y * dv;
        a[4 * k4 + 2] = v.z * dv; a[4 * k4 + 3] = v.w * dv;
    }
    float o[C_OUT];
#pragma unroll
    for (int j = 0; j < C_OUT; j++) o[j] = b2s[j];
#pragma unroll
    for (int k = 0; k < HID; k++) {
        float av = a[k];
#pragma unroll
        for (int j = 0; j < C_OUT; j++) o[j] += av * w2s[k * C_OUT + j];
    }
#pragma unroll
    for (int jg = 0; jg < C_OUT / 4; jg++) {
        float4 v = make_float4(o[4 * jg + 0], o[4 * jg + 1], o[4 * jg + 2], o[4 * jg + 3]);
        *(float4*)&out[(size_t)i * C_OUT + 4 * jg] = v;
    }
}

// ---------------- launcher ----------------
extern "C" void kernel_launch(void* const* d_in, const int* in_sizes, int n_in,
                              void* d_out, int out_size) {
    const float* x  = (const float*)d_in[0];
    const int*   ei = (const int*)d_in[1];
    const float* W1 = (const float*)d_in[2];
    const float* b1 = (const float*)d_in[3];
    const float* W2 = (const float*)d_in[4];
    const float* b2 = (const float*)d_in[5];
    float* out = (float*)d_out;

    const int N = in_sizes[0] / F_IN;
    const int E = in_sizes[1] / 2;
    const int* src = ei;
    const int* dst = ei + E;

    void *p;
    cudaGetSymbolAddress(&p, g_deg);  int*    deg  = (int*)p;
    cudaGetSymbolAddress(&p, g_dinv); float*  dinv = (float*)p;
    cudaGetSymbolAddress(&p, g_B1h);  __half* B1h  = (__half*)p;
    cudaGetSymbolAddress(&p, g_B2);   float*  B2   = (float*)p;
    cudaGetSymbolAddress(&p, g_W1h);  float*  W1h  = (float*)p;
    cudaGetSymbolAddress(&p, g_W1l);  float*  W1l  = (float*)p;

    const int TB = 256;
    const int nv4 = N * (HID / 4);

    // launch 0-2: zero+wsplit, degree, dinv
    k_zero_ws<<<(N + TB - 1) / TB, TB>>>(deg, W1, W1h, W1l, N, F_IN * HID);
    k_hist<<<(E + TB - 1) / TB, TB>>>(dst, deg, E);
    k_dinv<<<(N + TB - 1) / TB, TB>>>(deg, dinv, N);
    // launch 3 (profiled): h~ = dinv * (x @ W1) -> B1h (fp16) and B2 (fp32)
    k_gemm1<<<(N + 127) / 128, 256>>>(x, W1h, W1l, dinv, B1h, B2, N);
    // launch 4: B2 += A * B1h
    {
        int threads = E * 4;
        k_agg_h<<<(threads + TB - 1) / TB, TB>>>(src, dst, B1h, B2, E);
    }
    // launch 5: a~ -> B1h (fp16) and B2 (fp32 self-loop init)
    k_relubias<<<(nv4 + TB - 1) / TB, TB>>>((const float4*)B2, dinv, b1,
                                            B1h, (float4*)B2, N);
    // launch 6: B2 += A * B1h
    {
        int threads = E * 4;
        k_agg_h<<<(threads + TB - 1) / TB, TB>>>(src, dst, B1h, B2, E);
    }
    // launch 7: out = (dinv * B2) @ W2 + b2
    k_gemm2<<<(N + 127) / 128, 128>>>(B2, dinv, W2, b2, out, N);
}

// round 14
// speedup vs baseline: 1.0521x; 1.0521x over previous
#include <cuda_runtime.h>
#include <cuda_bf16.h>
#include <cuda_fp16.h>
#include <cstdint>

#define F_IN  512
#define HID   16
#define C_OUT 40
#define MAXN  100000
#define MAXE  3200000

typedef unsigned long long ull;
typedef unsigned int u32;

// ---------------- scratch (static device globals, no allocs) ----------------
__device__ __align__(128) int    g_deg [MAXN];
__device__ __align__(128) float  g_dinv[MAXN];
__device__ __align__(128) __half g_B1h [MAXN * HID];  // fp16 message buffer
__device__ __align__(128) float  g_B2  [MAXN * HID];  // fp32 agg accumulators
__device__ __align__(128) float  g_W1h [F_IN * HID];  // tf32 hi part of W1
__device__ __align__(128) float  g_W1l [F_IN * HID];  // tf32 lo part of W1

// ---------------- helpers ----------------
__device__ __forceinline__ void red4(float* p, float a, float b, float c, float d) {
    asm volatile("red.global.add.v4.f32 [%0], {%1,%2,%3,%4};"
                 :: "l"(p), "f"(a), "f"(b), "f"(c), "f"(d) : "memory");
}
__device__ __forceinline__ u32 s2u(const void* p) {
    u32 a;
    asm("{ .reg .u64 t; cvta.to.shared.u64 t, %1; cvt.u32.u64 %0, t; }"
        : "=r"(a) : "l"(p));
    return a;
}
__device__ __forceinline__ void cpa16(u32 dst, const void* src, int sz) {
    asm volatile("cp.async.cg.shared.global [%0], [%1], 16, %2;"
                 :: "r"(dst), "l"(src), "r"(sz) : "memory");
}
__device__ __forceinline__ void cpa_commit() {
    asm volatile("cp.async.commit_group;" ::: "memory");
}
template <int NN>
__device__ __forceinline__ void cpa_wait() {
    asm volatile("cp.async.wait_group %0;" :: "n"(NN) : "memory");
}
__device__ __forceinline__ u32 tf32_of(float f) {
    u32 r;
    asm("cvt.rna.tf32.f32 %0, %1;" : "=r"(r) : "f"(f));
    return r;
}
__device__ __forceinline__ void tf32_split(float a, u32& hi, u32& lo) {
    hi = tf32_of(a);
    lo = tf32_of(a - __uint_as_float(hi));
}
__device__ __forceinline__ void mma_tf32(float& d0, float& d1, float& d2, float& d3,
                                         u32 a0, u32 a1, u32 a2, u32 a3,
                                         u32 b0, u32 b1) {
    asm("mma.sync.aligned.m16n8k8.row.col.f32.tf32.tf32.f32 "
        "{%0,%1,%2,%3}, {%4,%5,%6,%7}, {%8,%9}, {%0,%1,%2,%3};"
        : "+f"(d0), "+f"(d1), "+f"(d2), "+f"(d3)
        : "r"(a0), "r"(a1), "r"(a2), "r"(a3), "r"(b0), "r"(b1));
}

// ---------------- launch 0: fused zero(deg) + W1 tf32 split -----------------
__global__ void k_zero_ws(int* deg, const float* __restrict__ W1,
                          float* wh, float* wl, int N, int nw) {
    int i = blockIdx.x * blockDim.x + threadIdx.x;
    if (i < N) deg[i] = 0;
    if (i < nw) {
        float w = W1[i];
        u32 h, l;
        tf32_split(w, h, l);
        wh[i] = __uint_as_float(h);
        wl[i] = __uint_as_float(l);
    }
}
__global__ void k_hist(const int* __restrict__ dst, int* deg, int E) {
    int i = blockIdx.x * blockDim.x + threadIdx.x;
    if (i < E) atomicAdd(&deg[dst[i]], 1);
}
__global__ void k_dinv(const int* __restrict__ deg, float* dinv, int N) {
    int i = blockIdx.x * blockDim.x + threadIdx.x;
    if (i < N) dinv[i] = rsqrtf((float)(deg[i] + 1));
}

// ------ GEMM1 v9: tf32 mma 2-term, 3-stage cp.async pipeline, 16-k stages ---
#define G1_NS 3      // pipeline stages
#define G1_XS 20     // x row stride (16 data + 4 pad), conflict-free A-frags
#define G1_WS 24     // w row stride, conflict-free B-frags
#define G1_XSZ (128 * G1_XS)   // floats per x stage
#define G1_WSZ (16 * G1_WS)    // floats per w stage (per hi/lo)
__global__ __launch_bounds__(256) void k_gemm1(const float* __restrict__ x,
                                               const float* __restrict__ W1h,
                                               const float* __restrict__ W1l,
                                               const float* __restrict__ dinv,
                                               __half* __restrict__ h0h,
                                               float* __restrict__ h1, int N) {
    __shared__ __align__(16) float xs3[G1_NS][G1_XSZ];   // 3 x 10KB
    __shared__ __align__(16) float wh3[G1_NS][G1_WSZ];   // 3 x 1.5KB
    __shared__ __align__(16) float wl3[G1_NS][G1_WSZ];   // 3 x 1.5KB
    const int t    = threadIdx.x;
    const int lane = t & 31;
    const int wid  = t >> 5;
    const int gid  = lane >> 2;
    const int tig  = lane & 3;
    const int base = blockIdx.x * 128;

    // x staging: 512 chunks (128 rows x 4), 2 per thread
    u32 xoff[2];          // smem float-offset within a stage
    const float* xsrc[2];
    int xsz[2];
#pragma unroll
    for (int j = 0; j < 2; j++) {
        int idx = t + 256 * j;
        int r = idx >> 2, q = idx & 3;
        xoff[j] = r * G1_XS + q * 4;
        xsrc[j] = x + (size_t)(base + r) * F_IN + q * 4;
        xsz[j]  = (base + r < N) ? 16 : 0;
    }
    // w staging: 64 chunks hi (t<64), 64 chunks lo (64<=t<128)
    const int wc = t & 63;
    const int wkk = wc >> 2, wq = wc & 3;
    const u32 woff = wkk * G1_WS + wq * 4;
    const float* wsrcb = ((t & 127) < 64 ? W1h : W1l) + (size_t)wkk * 16 + wq * 4;
    const bool do_w = (t < 128);
    const bool w_hi = (t < 64);

    float d0[4] = {0.f, 0.f, 0.f, 0.f};
    float d1[4] = {0.f, 0.f, 0.f, 0.f};

    // prologue: prefetch stages 0..2
#pragma unroll
    for (int s = 0; s < G1_NS; s++) {
        const int kg = s * 16;
        if (do_w) {
            float* wbase = w_hi ? &wh3[s][0] : &wl3[s][0];
            cpa16(s2u(wbase) + woff * 4, wsrcb + (size_t)kg * 16, 16);
        }
#pragma unroll
        for (int j = 0; j < 2; j++)
            cpa16(s2u(&xs3[s][0]) + xoff[j] * 4, xsrc[j] + kg, xsz[j]);
        cpa_commit();
    }

    const int ra = wid * 16 + gid;
    for (int kt = 0; kt < 32; kt++) {
        const int buf = kt % G1_NS;
        cpa_wait<G1_NS - 1>();
        __syncthreads();

#pragma unroll
        for (int s = 0; s < 2; s++) {
            const int ko = s * 8;
            float a0 = xs3[buf][ra * G1_XS + ko + tig];
            float a1 = xs3[buf][(ra + 8) * G1_XS + ko + tig];
            float a2 = xs3[buf][ra * G1_XS + ko + tig + 4];
            float a3 = xs3[buf][(ra + 8) * G1_XS + ko + tig + 4];
            u32 a0h = tf32_of(a0), a1h = tf32_of(a1);
            u32 a2h = tf32_of(a2), a3h = tf32_of(a3);
            u32 b0h = __float_as_uint(wh3[buf][(ko + tig) * G1_WS + gid]);
            u32 b1h = __float_as_uint(wh3[buf][(ko + tig + 4) * G1_WS + gid]);
            u32 b2h = __float_as_uint(wh3[buf][(ko + tig) * G1_WS + gid + 8]);
            u32 b3h = __float_as_uint(wh3[buf][(ko + tig + 4) * G1_WS + gid + 8]);
            u32 b0l = __float_as_uint(wl3[buf][(ko + tig) * G1_WS + gid]);
            u32 b1l = __float_as_uint(wl3[buf][(ko + tig + 4) * G1_WS + gid]);
            u32 b2l = __float_as_uint(wl3[buf][(ko + tig) * G1_WS + gid + 8]);
            u32 b3l = __float_as_uint(wl3[buf][(ko + tig + 4) * G1_WS + gid + 8]);

            // 2-term: a_hi*b_hi + a_hi*b_lo
            mma_tf32(d0[0], d0[1], d0[2], d0[3], a0h, a1h, a2h, a3h, b0h, b1h);
            mma_tf32(d1[0], d1[1], d1[2], d1[3], a0h, a1h, a2h, a3h, b2h, b3h);
            mma_tf32(d0[0], d0[1], d0[2], d0[3], a0h, a1h, a2h, a3h, b0l, b1l);
            mma_tf32(d1[0], d1[1], d1[2], d1[3], a0h, a1h, a2h, a3h, b2l, b3l);
        }
        __syncthreads();

        const int ktp = kt + G1_NS;
        if (ktp < 32) {
            const int kg = ktp * 16;
            if (do_w) {
                float* wbase = w_hi ? &wh3[buf][0] : &wl3[buf][0];
                cpa16(s2u(wbase) + woff * 4, wsrcb + (size_t)kg * 16, 16);
            }
#pragma unroll
            for (int j = 0; j < 2; j++)
                cpa16(s2u(&xs3[buf][0]) + xoff[j] * 4, xsrc[j] + kg, xsz[j]);
        }
        cpa_commit();   // commit every iter to keep group count aligned
    }

    // epilogue: scale by dinv; fp16 -> h0h (messages), fp32 -> h1 (self-loop)
    {
        int r0 = base + wid * 16 + gid;
        int r1 = r0 + 8;
        if (r0 < N) {
            float dv = dinv[r0];
            float4 v = make_float4(d0[0] * dv, d0[1] * dv, d1[0] * dv, d1[1] * dv);
            *(__half2*)&h0h[(size_t)r0 * HID + 2 * tig]     = __floats2half2_rn(v.x, v.y);
            *(__half2*)&h0h[(size_t)r0 * HID + 8 + 2 * tig] = __floats2half2_rn(v.z, v.w);
            *(float2*)&h1[(size_t)r0 * HID + 2 * tig]     = make_float2(v.x, v.y);
            *(float2*)&h1[(size_t)r0 * HID + 8 + 2 * tig] = make_float2(v.z, v.w);
        }
        if (r1 < N) {
            float dv = dinv[r1];
            float4 v = make_float4(d0[2] * dv, d0[3] * dv, d1[2] * dv, d1[3] * dv);
            *(__half2*)&h0h[(size_t)r1 * HID + 2 * tig]     = __floats2half2_rn(v.x, v.y);
            *(__half2*)&h0h[(size_t)r1 * HID + 8 + 2 * tig] = __floats2half2_rn(v.z, v.w);
            *(float2*)&h1[(size_t)r1 * HID + 2 * tig]     = make_float2(v.x, v.y);
            *(float2*)&h1[(size_t)r1 * HID + 8 + 2 * tig] = make_float2(v.z, v.w);
        }
    }
}

// --- edge aggregation: fp16 gather (uint2/thread), fp32 red4, 4 thr/edge ---
__global__ void k_agg_h(const int* __restrict__ src, const int* __restrict__ dst,
                        const __half* __restrict__ inh, float* out, int E) {
    int tid = blockIdx.x * blockDim.x + threadIdx.x;
    int e = tid >> 2;
    int c = tid & 3;
    if (e < E) {
        int s = src[e];
        int d = dst[e];
        uint2 v = __ldg((const uint2*)(inh + (size_t)s * HID) + c);  // 4 halves
        float2 f0 = __half22float2(*(__half2*)&v.x);
        float2 f1 = __half22float2(*(__half2*)&v.y);
        red4(out + (size_t)d * HID + c * 4, f0.x, f0.y, f1.x, f1.y);
    }
}

// -------- a~ = dinv * relu(dinv * y1 + b1): fp16 -> o0h, fp32 -> o1 ---------
__global__ void k_relubias(const float4* __restrict__ in4, const float* __restrict__ dinv,
                           const float* __restrict__ b1,
                           __half* __restrict__ o0h, float4* __restrict__ o1, int N) {
    int i = blockIdx.x * blockDim.x + threadIdx.x;
    if (i < N * (HID / 4)) {
        float dv = dinv[i >> 2];
        int jb = (i & 3) * 4;
        float4 v = in4[i];
        v.x = fmaxf(fmaf(v.x, dv, b1[jb + 0]), 0.f) * dv;
        v.y = fmaxf(fmaf(v.y, dv, b1[jb + 1]), 0.f) * dv;
        v.z = fmaxf(fmaf(v.z, dv, b1[jb + 2]), 0.f) * dv;
        v.w = fmaxf(fmaf(v.w, dv, b1[jb + 3]), 0.f) * dv;
        __half2 ha = __floats2half2_rn(v.x, v.y);
        __half2 hb = __floats2half2_rn(v.z, v.w);
        *(uint2*)&o0h[(size_t)i * 4] = make_uint2(*(u32*)&ha, *(u32*)&hb);
        o1[i] = v;
    }
}

// ---------------- GEMM2 + b2 ----------------
__global__ __launch_bounds__(128) void k_gemm2(const float* __restrict__ y2,
                                               const float* __restrict__ dinv,
                                               const float* __restrict__ W2,
                                               const float* __restrict__ b2,
                                               float* __restrict__ out, int N) {
    __shared__ float w2s[HID * C_OUT];
    __shared__ float b2s[C_OUT];
    int t = threadIdx.x;
    for (int i = t; i < HID * C_OUT; i += 128) w2s[i] = W2[i];
    if (t < C_OUT) b2s[t] = b2[t];
    __syncthreads();
    int i = blockIdx.x * 128 + t;
    if (i >= N) return;
    float dv = dinv[i];
    float a[HID];
#pragma unroll
    for (int k4 = 0; k4 < 4; k4++) {
        float4 v = *(const float4*)&y2[(size_t)i * HID + 4 * k4];
        a[4 * k4 + 0] = v.x * dv; a[4 * k4 + 1] = v.y * dv;
        a[4 * k4 + 2] = v.z * dv; a[4 * k4 + 3] = v.w * dv;
    }
    float o[C_OUT];
#pragma unroll
    for (int j = 0; j < C_OUT; j++) o[j] = b2s[j];
#pragma unroll
    for (int k = 0; k < HID; k++) {
        float av = a[k];
#pragma unroll
        for (int j = 0; j < C_OUT; j++) o[j] += av * w2s[k * C_OUT + j];
    }
#pragma unroll
    for (int jg = 0; jg < C_OUT / 4; jg++) {
        float4 v = make_float4(o[4 * jg + 0], o[4 * jg + 1], o[4 * jg + 2], o[4 * jg + 3]);
        *(float4*)&out[(size_t)i * C_OUT + 4 * jg] = v;
    }
}

// ---------------- launcher ----------------
extern "C" void kernel_launch(void* const* d_in, const int* in_sizes, int n_in,
                              void* d_out, int out_size) {
    const float* x  = (const float*)d_in[0];
    const int*   ei = (const int*)d_in[1];
    const float* W1 = (const float*)d_in[2];
    const float* b1 = (const float*)d_in[3];
    const float* W2 = (const float*)d_in[4];
    const float* b2 = (const float*)d_in[5];
    float* out = (float*)d_out;

    const int N = in_sizes[0] / F_IN;
    const int E = in_sizes[1] / 2;
    const int* src = ei;
    const int* dst = ei + E;

    void *p;
    cudaGetSymbolAddress(&p, g_deg);  int*    deg  = (int*)p;
    cudaGetSymbolAddress(&p, g_dinv); float*  dinv = (float*)p;
    cudaGetSymbolAddress(&p, g_B1h);  __half* B1h  = (__half*)p;
    cudaGetSymbolAddress(&p, g_B2);   float*  B2   = (float*)p;
    cudaGetSymbolAddress(&p, g_W1h);  float*  W1h  = (float*)p;
    cudaGetSymbolAddress(&p, g_W1l);  float*  W1l  = (float*)p;

    const int TB = 256;
    const int nv4 = N * (HID / 4);

    // launch 0-2: zero+wsplit, degree, dinv
    k_zero_ws<<<(N + TB - 1) / TB, TB>>>(deg, W1, W1h, W1l, N, F_IN * HID);
    k_hist<<<(E + TB - 1) / TB, TB>>>(dst, deg, E);
    k_dinv<<<(N + TB - 1) / TB, TB>>>(deg, dinv, N);
    // launch 3 (profiled): h~ = dinv * (x @ W1) -> B1h (fp16) and B2 (fp32)
    k_gemm1<<<(N + 127) / 128, 256>>>(x, W1h, W1l, dinv, B1h, B2, N);
    // launch 4: B2 += A * B1h
    {
        int threads = E * 4;
        k_agg_h<<<(threads + TB - 1) / TB, TB>>>(src, dst, B1h, B2, E);
    }
    // launch 5: a~ -> B1h (fp16) and B2 (fp32 self-loop init)
    k_relubias<<<(nv4 + TB - 1) / TB, TB>>>((const float4*)B2, dinv, b1,
                                            B1h, (float4*)B2, N);
    // launch 6: B2 += A * B1h
    {
        int threads = E * 4;
        k_agg_h<<<(threads + TB - 1) / TB, TB>>>(src, dst, B1h, B2, E);
    }
    // launch 7: out = (dinv * B2) @ W2 + b2
    k_gemm2<<<(N + 127) / 128, 128>>>(B2, dinv, W2, b2, out, N);
}

// round 15
// speedup vs baseline: 1.0671x; 1.0142x over previous
#include <cuda_runtime.h>
#include <cuda_bf16.h>
#include <cuda_fp16.h>
#include <cstdint>

#define F_IN  512
#define HID   16
#define C_OUT 40
#define MAXN  100000
#define MAXE  3200000

typedef unsigned long long ull;
typedef unsigned int u32;

// ---------------- scratch (static device globals, no allocs) ----------------
// g_deg is zero-initialized at module load; k_gemm2 re-zeros it each call,
// so the "deg starts at zero" invariant holds across all graph replays.
__device__ __align__(128) int    g_deg [MAXN];
__device__ __align__(128) __half g_B1h [MAXN * HID];  // fp16 message buffer
__device__ __align__(128) float  g_B2  [MAXN * HID];  // fp32 agg accumulators
__device__ __align__(128) float  g_W1h [F_IN * HID];  // tf32 hi part of W1
__device__ __align__(128) float  g_W1l [F_IN * HID];  // tf32 lo part of W1

// ---------------- helpers ----------------
__device__ __forceinline__ void red4(float* p, float a, float b, float c, float d) {
    asm volatile("red.global.add.v4.f32 [%0], {%1,%2,%3,%4};"
                 :: "l"(p), "f"(a), "f"(b), "f"(c), "f"(d) : "memory");
}
__device__ __forceinline__ u32 s2u(const void* p) {
    u32 a;
    asm("{ .reg .u64 t; cvta.to.shared.u64 t, %1; cvt.u32.u64 %0, t; }"
        : "=r"(a) : "l"(p));
    return a;
}
__device__ __forceinline__ void cpa16(u32 dst, const void* src, int sz) {
    asm volatile("cp.async.cg.shared.global [%0], [%1], 16, %2;"
                 :: "r"(dst), "l"(src), "r"(sz) : "memory");
}
__device__ __forceinline__ void cpa_commit() {
    asm volatile("cp.async.commit_group;" ::: "memory");
}
template <int NN>
__device__ __forceinline__ void cpa_wait() {
    asm volatile("cp.async.wait_group %0;" :: "n"(NN) : "memory");
}
__device__ __forceinline__ u32 tf32_of(float f) {
    u32 r;
    asm("cvt.rna.tf32.f32 %0, %1;" : "=r"(r) : "f"(f));
    return r;
}
__device__ __forceinline__ void tf32_split(float a, u32& hi, u32& lo) {
    hi = tf32_of(a);
    lo = tf32_of(a - __uint_as_float(hi));
}
__device__ __forceinline__ void mma_tf32(float& d0, float& d1, float& d2, float& d3,
                                         u32 a0, u32 a1, u32 a2, u32 a3,
                                         u32 b0, u32 b1) {
    asm("mma.sync.aligned.m16n8k8.row.col.f32.tf32.tf32.f32 "
        "{%0,%1,%2,%3}, {%4,%5,%6,%7}, {%8,%9}, {%0,%1,%2,%3};"
        : "+f"(d0), "+f"(d1), "+f"(d2), "+f"(d3)
        : "r"(a0), "r"(a1), "r"(a2), "r"(a3), "r"(b0), "r"(b1));
}

// ------- launch 0: degree histogram + W1 tf32 split (fused) ----------------
__global__ void k_hist_ws(const int* __restrict__ dst, int* deg,
                          const float* __restrict__ W1, float* wh, float* wl,
                          int E, int nw) {
    int i = blockIdx.x * blockDim.x + threadIdx.x;
    if (i < nw) {
        float w = W1[i];
        u32 h, l;
        tf32_split(w, h, l);
        wh[i] = __uint_as_float(h);
        wl[i] = __uint_as_float(l);
    }
    if (i < E) atomicAdd(&deg[dst[i]], 1);
}

// ------ GEMM1 v9: tf32 mma 2-term, 3-stage cp.async pipeline ----------------
#define G1_NS 3
#define G1_XS 20
#define G1_WS 24
#define G1_XSZ (128 * G1_XS)
#define G1_WSZ (16 * G1_WS)
__global__ __launch_bounds__(256) void k_gemm1(const float* __restrict__ x,
                                               const float* __restrict__ W1h,
                                               const float* __restrict__ W1l,
                                               const int* __restrict__ deg,
                                               __half* __restrict__ h0h,
                                               float* __restrict__ h1, int N) {
    __shared__ __align__(16) float xs3[G1_NS][G1_XSZ];
    __shared__ __align__(16) float wh3[G1_NS][G1_WSZ];
    __shared__ __align__(16) float wl3[G1_NS][G1_WSZ];
    const int t    = threadIdx.x;
    const int lane = t & 31;
    const int wid  = t >> 5;
    const int gid  = lane >> 2;
    const int tig  = lane & 3;
    const int base = blockIdx.x * 128;

    u32 xoff[2];
    const float* xsrc[2];
    int xsz[2];
#pragma unroll
    for (int j = 0; j < 2; j++) {
        int idx = t + 256 * j;
        int r = idx >> 2, q = idx & 3;
        xoff[j] = r * G1_XS + q * 4;
        xsrc[j] = x + (size_t)(base + r) * F_IN + q * 4;
        xsz[j]  = (base + r < N) ? 16 : 0;
    }
    const int wc = t & 63;
    const int wkk = wc >> 2, wq = wc & 3;
    const u32 woff = wkk * G1_WS + wq * 4;
    const float* wsrcb = ((t & 127) < 64 ? W1h : W1l) + (size_t)wkk * 16 + wq * 4;
    const bool do_w = (t < 128);
    const bool w_hi = (t < 64);

    float d0[4] = {0.f, 0.f, 0.f, 0.f};
    float d1[4] = {0.f, 0.f, 0.f, 0.f};

#pragma unroll
    for (int s = 0; s < G1_NS; s++) {
        const int kg = s * 16;
        if (do_w) {
            float* wbase = w_hi ? &wh3[s][0] : &wl3[s][0];
            cpa16(s2u(wbase) + woff * 4, wsrcb + (size_t)kg * 16, 16);
        }
#pragma unroll
        for (int j = 0; j < 2; j++)
            cpa16(s2u(&xs3[s][0]) + xoff[j] * 4, xsrc[j] + kg, xsz[j]);
        cpa_commit();
    }

    const int ra = wid * 16 + gid;
    for (int kt = 0; kt < 32; kt++) {
        const int buf = kt % G1_NS;
        cpa_wait<G1_NS - 1>();
        __syncthreads();

#pragma unroll
        for (int s = 0; s < 2; s++) {
            const int ko = s * 8;
            float a0 = xs3[buf][ra * G1_XS + ko + tig];
            float a1 = xs3[buf][(ra + 8) * G1_XS + ko + tig];
            float a2 = xs3[buf][ra * G1_XS + ko + tig + 4];
            float a3 = xs3[buf][(ra + 8) * G1_XS + ko + tig + 4];
            u32 a0h = tf32_of(a0), a1h = tf32_of(a1);
            u32 a2h = tf32_of(a2), a3h = tf32_of(a3);
            u32 b0h = __float_as_uint(wh3[buf][(ko + tig) * G1_WS + gid]);
            u32 b1h = __float_as_uint(wh3[buf][(ko + tig + 4) * G1_WS + gid]);
            u32 b2h = __float_as_uint(wh3[buf][(ko + tig) * G1_WS + gid + 8]);
            u32 b3h = __float_as_uint(wh3[buf][(ko + tig + 4) * G1_WS + gid + 8]);
            u32 b0l = __float_as_uint(wl3[buf][(ko + tig) * G1_WS + gid]);
            u32 b1l = __float_as_uint(wl3[buf][(ko + tig + 4) * G1_WS + gid]);
            u32 b2l = __float_as_uint(wl3[buf][(ko + tig) * G1_WS + gid + 8]);
            u32 b3l = __float_as_uint(wl3[buf][(ko + tig + 4) * G1_WS + gid + 8]);

            mma_tf32(d0[0], d0[1], d0[2], d0[3], a0h, a1h, a2h, a3h, b0h, b1h);
            mma_tf32(d1[0], d1[1], d1[2], d1[3], a0h, a1h, a2h, a3h, b2h, b3h);
            mma_tf32(d0[0], d0[1], d0[2], d0[3], a0h, a1h, a2h, a3h, b0l, b1l);
            mma_tf32(d1[0], d1[1], d1[2], d1[3], a0h, a1h, a2h, a3h, b2l, b3l);
        }
        __syncthreads();

        const int ktp = kt + G1_NS;
        if (ktp < 32) {
            const int kg = ktp * 16;
            if (do_w) {
                float* wbase = w_hi ? &wh3[buf][0] : &wl3[buf][0];
                cpa16(s2u(wbase) + woff * 4, wsrcb + (size_t)kg * 16, 16);
            }
#pragma unroll
            for (int j = 0; j < 2; j++)
                cpa16(s2u(&xs3[buf][0]) + xoff[j] * 4, xsrc[j] + kg, xsz[j]);
        }
        cpa_commit();
    }

    // epilogue: dinv computed on the fly from deg
    {
        int r0 = base + wid * 16 + gid;
        int r1 = r0 + 8;
        if (r0 < N) {
            float dv = rsqrtf((float)(deg[r0] + 1));
            float4 v = make_float4(d0[0] * dv, d0[1] * dv, d1[0] * dv, d1[1] * dv);
            *(__half2*)&h0h[(size_t)r0 * HID + 2 * tig]     = __floats2half2_rn(v.x, v.y);
            *(__half2*)&h0h[(size_t)r0 * HID + 8 + 2 * tig] = __floats2half2_rn(v.z, v.w);
            *(float2*)&h1[(size_t)r0 * HID + 2 * tig]     = make_float2(v.x, v.y);
            *(float2*)&h1[(size_t)r0 * HID + 8 + 2 * tig] = make_float2(v.z, v.w);
        }
        if (r1 < N) {
            float dv = rsqrtf((float)(deg[r1] + 1));
            float4 v = make_float4(d0[2] * dv, d0[3] * dv, d1[2] * dv, d1[3] * dv);
            *(__half2*)&h0h[(size_t)r1 * HID + 2 * tig]     = __floats2half2_rn(v.x, v.y);
            *(__half2*)&h0h[(size_t)r1 * HID + 8 + 2 * tig] = __floats2half2_rn(v.z, v.w);
            *(float2*)&h1[(size_t)r1 * HID + 2 * tig]     = make_float2(v.x, v.y);
            *(float2*)&h1[(size_t)r1 * HID + 8 + 2 * tig] = make_float2(v.z, v.w);
        }
    }
}

// --- edge aggregation: fp16 gather (uint2/thread), fp32 red4, 4 thr/edge ---
__global__ void k_agg_h(const int* __restrict__ src, const int* __restrict__ dst,
                        const __half* __restrict__ inh, float* out, int E) {
    int tid = blockIdx.x * blockDim.x + threadIdx.x;
    int e = tid >> 2;
    int c = tid & 3;
    if (e < E) {
        int s = src[e];
        int d = dst[e];
        uint2 v = __ldg((const uint2*)(inh + (size_t)s * HID) + c);
        float2 f0 = __half22float2(*(__half2*)&v.x);
        float2 f1 = __half22float2(*(__half2*)&v.y);
        red4(out + (size_t)d * HID + c * 4, f0.x, f0.y, f1.x, f1.y);
    }
}

// -------- a~ = dinv * relu(dinv * y1 + b1): fp16 -> o0h, fp32 -> o1 ---------
__global__ void k_relubias(const float4* __restrict__ in4, const int* __restrict__ deg,
                           const float* __restrict__ b1,
                           __half* __restrict__ o0h, float4* __restrict__ o1, int N) {
    int i = blockIdx.x * blockDim.x + threadIdx.x;
    if (i < N * (HID / 4)) {
        float dv = rsqrtf((float)(deg[i >> 2] + 1));
        int jb = (i & 3) * 4;
        float4 v = in4[i];
        v.x = fmaxf(fmaf(v.x, dv, b1[jb + 0]), 0.f) * dv;
        v.y = fmaxf(fmaf(v.y, dv, b1[jb + 1]), 0.f) * dv;
        v.z = fmaxf(fmaf(v.z, dv, b1[jb + 2]), 0.f) * dv;
        v.w = fmaxf(fmaf(v.w, dv, b1[jb + 3]), 0.f) * dv;
        __half2 ha = __floats2half2_rn(v.x, v.y);
        __half2 hb = __floats2half2_rn(v.z, v.w);
        *(uint2*)&o0h[(size_t)i * 4] = make_uint2(*(u32*)&ha, *(u32*)&hb);
        o1[i] = v;
    }
}

// ------- GEMM2 + b2; also resets deg to 0 for the next graph replay --------
__global__ __launch_bounds__(128) void k_gemm2(const float* __restrict__ y2,
                                               int* deg,
                                               const float* __restrict__ W2,
                                               const float* __restrict__ b2,
                                               float* __restrict__ out, int N) {
    __shared__ float w2s[HID * C_OUT];
    __shared__ float b2s[C_OUT];
    int t = threadIdx.x;
    for (int i = t; i < HID * C_OUT; i += 128) w2s[i] = W2[i];
    if (t < C_OUT) b2s[t] = b2[t];
    __syncthreads();
    int i = blockIdx.x * 128 + t;
    if (i >= N) return;
    float dv = rsqrtf((float)(deg[i] + 1));
    deg[i] = 0;   // self-clean for next call
    float a[HID];
#pragma unroll
    for (int k4 = 0; k4 < 4; k4++) {
        float4 v = *(const float4*)&y2[(size_t)i * HID + 4 * k4];
        a[4 * k4 + 0] = v.x * dv; a[4 * k4 + 1] = v.y * dv;
        a[4 * k4 + 2] = v.z * dv; a[4 * k4 + 3] = v.w * dv;
    }
    float o[C_OUT];
#pragma unroll
    for (int j = 0; j < C_OUT; j++) o[j] = b2s[j];
#pragma unroll
    for (int k = 0; k < HID; k++) {
        float av = a[k];
#pragma unroll
        for (int j = 0; j < C_OUT; j++) o[j] += av * w2s[k * C_OUT + j];
    }
#pragma unroll
    for (int jg = 0; jg < C_OUT / 4; jg++) {
        float4 v = make_float4(o[4 * jg + 0], o[4 * jg + 1], o[4 * jg + 2], o[4 * jg + 3]);
        *(float4*)&out[(size_t)i * C_OUT + 4 * jg] = v;
    }
}

// ---------------- launcher (6 graph nodes) ----------------
extern "C" void kernel_launch(void* const* d_in, const int* in_sizes, int n_in,
                              void* d_out, int out_size) {
    const float* x  = (const float*)d_in[0];
    const int*   ei = (const int*)d_in[1];
    const float* W1 = (const float*)d_in[2];
    const float* b1 = (const float*)d_in[3];
    const float* W2 = (const float*)d_in[4];
    const float* b2 = (const float*)d_in[5];
    float* out = (float*)d_out;

    const int N = in_sizes[0] / F_IN;
    const int E = in_sizes[1] / 2;
    const int* src = ei;
    const int* dst = ei + E;

    void *p;
    cudaGetSymbolAddress(&p, g_deg);  int*    deg  = (int*)p;
    cudaGetSymbolAddress(&p, g_B1h);  __half* B1h  = (__half*)p;
    cudaGetSymbolAddress(&p, g_B2);   float*  B2   = (float*)p;
    cudaGetSymbolAddress(&p, g_W1h);  float*  W1h  = (float*)p;
    cudaGetSymbolAddress(&p, g_W1l);  float*  W1l  = (float*)p;

    const int TB = 256;
    const int nv4 = N * (HID / 4);

    // 0: degree histogram + W1 split (deg arrives zeroed: module init / gemm2)
    k_hist_ws<<<(E + TB - 1) / TB, TB>>>(dst, deg, W1, W1h, W1l, E, F_IN * HID);
    // 1: h~ = dinv * (x @ W1) -> B1h (fp16) and B2 (fp32 self-loop init)
    k_gemm1<<<(N + 127) / 128, 256>>>(x, W1h, W1l, deg, B1h, B2, N);
    // 2: B2 += A * B1h
    {
        int threads = E * 4;
        k_agg_h<<<(threads + TB - 1) / TB, TB>>>(src, dst, B1h, B2, E);
    }
    // 3: a~ -> B1h (fp16) and B2 (fp32 self-loop init)
    k_relubias<<<(nv4 + TB - 1) / TB, TB>>>((const float4*)B2, deg, b1,
                                            B1h, (float4*)B2, N);
    // 4: B2 += A * B1h
    {
        int threads = E * 4;
        k_agg_h<<<(threads + TB - 1) / TB, TB>>>(src, dst, B1h, B2, E);
    }
    // 5: out = (dinv * B2) @ W2 + b2 ; deg reset
    k_gemm2<<<(N + 127) / 128, 128>>>(B2, deg, W2, b2, out, N);
}